// round 1
// baseline (speedup 1.0000x reference)
#include <cuda_runtime.h>
#include <cstdint>

// Problem constants (fixed by setup_inputs)
#define B      8
#define C      64
#define NPTS   100000
#define RES    32
#define NVOX   (RES * RES * RES)   // 32768

// ---------------------------------------------------------------------------
// Scratch (static __device__ globals: the sanctioned no-alloc scratch path).
// g_sums is channel-contiguous so one point's 64 adds are 16 aligned float4s.
// All scratch is zero at module load; finalize_kernel restores zeros after
// consuming it, so every graph replay sees a clean state.
// ---------------------------------------------------------------------------
__device__ float g_mean[B][3];
__device__ float g_cnt [B][NVOX];
__device__ float g_sums[B][NVOX][C];   // 64 MB

// ---------------------------------------------------------------------------
// Kernel 1: per-(batch, dim) mean over N points.  grid = (3, B), 256 threads.
// ---------------------------------------------------------------------------
__global__ void mean_kernel(const float* __restrict__ coords)
{
    const int d = blockIdx.x;
    const int b = blockIdx.y;
    const float* p = coords + (size_t)(b * 3 + d) * NPTS;

    float s = 0.0f;
    for (int i = threadIdx.x; i < NPTS; i += 256)
        s += p[i];

    __shared__ float sm[8];
    #pragma unroll
    for (int o = 16; o; o >>= 1)
        s += __shfl_down_sync(0xFFFFFFFFu, s, o);
    if ((threadIdx.x & 31) == 0) sm[threadIdx.x >> 5] = s;
    __syncthreads();
    if (threadIdx.x < 8) {
        s = sm[threadIdx.x];
        #pragma unroll
        for (int o = 4; o; o >>= 1)
            s += __shfl_down_sync(0xFFu, s, o);
        if (threadIdx.x == 0)
            g_mean[b][d] = s * (1.0f / (float)NPTS);
    }
}

// ---------------------------------------------------------------------------
// Kernel 2: per-point scatter.  One thread per point.
//  - computes clipped normalized coords (written to output tail)
//  - voxel index, count atomic
//  - 16x red.global.add.v4.f32 into channel-contiguous scratch
// ---------------------------------------------------------------------------
__global__ void scatter_kernel(const float* __restrict__ feat,
                               const float* __restrict__ coords,
                               float* __restrict__ norm_out)
{
    const int n = blockIdx.x * blockDim.x + threadIdx.x;
    const int b = blockIdx.y;
    if (n >= NPTS) return;

    int vc[3];
    #pragma unroll
    for (int d = 0; d < 3; d++) {
        const size_t off = (size_t)(b * 3 + d) * NPTS + n;
        float v = (coords[off] - g_mean[b][d] + 1.0f) * 0.5f;   // (x-mean+1)/2
        float w = fminf(fmaxf(v * (float)RES, 0.0f), (float)(RES - 1));
        norm_out[off] = w;                                       // clipped*R is the returned norm_coords
        vc[d] = (int)rintf(w);                                   // round-half-even == jnp.round
    }
    const int idx = vc[0] * (RES * RES) + vc[1] * RES + vc[2];

    atomicAdd(&g_cnt[b][idx], 1.0f);

    const float* f   = feat + (size_t)b * C * NPTS + n;
    float*       dst = &g_sums[b][idx][0];

    #pragma unroll
    for (int c = 0; c < C; c += 4) {
        float a0 = f[(size_t)(c + 0) * NPTS];
        float a1 = f[(size_t)(c + 1) * NPTS];
        float a2 = f[(size_t)(c + 2) * NPTS];
        float a3 = f[(size_t)(c + 3) * NPTS];
        asm volatile("red.global.add.v4.f32 [%0], {%1,%2,%3,%4};"
                     :: "l"(dst + c), "f"(a0), "f"(a1), "f"(a2), "f"(a3)
                     : "memory");
    }
}

// ---------------------------------------------------------------------------
// Kernel 3: finalize.  Each block: 32 voxels x 64 channels tile.
//  - load scratch coalesced ([vox][chan] rows), scale by 1/max(cnt,1)
//  - transpose via padded smem
//  - write output coalesced in [chan][vox] layout
//  - restore scratch to zero for the next graph replay
// grid = (NVOX/32, B), 256 threads.
// ---------------------------------------------------------------------------
__global__ void finalize_kernel(float* __restrict__ vox_out)
{
    const int b   = blockIdx.y;
    const int v0  = blockIdx.x * 32;
    const int tid = threadIdx.x;

    __shared__ float sm[32 * 65];   // pad 65 -> conflict-free transpose
    __shared__ float inv[32];

    if (tid < 32) {
        float cnt = g_cnt[b][v0 + tid];
        g_cnt[b][v0 + tid] = 0.0f;                 // re-zero for next replay
        inv[tid] = 1.0f / fmaxf(cnt, 1.0f);
    }
    __syncthreads();

    #pragma unroll
    for (int k = 0; k < 8; k++) {
        const int e = k * 256 + tid;
        const int c = e & 63;
        const int v = e >> 6;
        float* sp = &g_sums[b][v0 + v][c];
        float val = *sp;
        *sp = 0.0f;                                // re-zero for next replay
        sm[v * 65 + c] = val * inv[v];
    }
    __syncthreads();

    #pragma unroll
    for (int k = 0; k < 8; k++) {
        const int c = k * 8 + (tid >> 5);
        const int v = tid & 31;
        vox_out[((size_t)(b * C + c)) * NVOX + v0 + v] = sm[v * 65 + c];
    }
}

// ---------------------------------------------------------------------------
// Launch: inputs per metadata order: [0]=features f32 [B,C,N], [1]=coords f32 [B,3,N]
// Output buffer: vox [B,C,32,32,32] followed by norm_coords [B,3,N], both f32.
// ---------------------------------------------------------------------------
extern "C" void kernel_launch(void* const* d_in, const int* in_sizes, int n_in,
                              void* d_out, int out_size)
{
    const float* feat   = (const float*)d_in[0];
    const float* coords = (const float*)d_in[1];
    float* out      = (float*)d_out;
    float* norm_out = out + (size_t)B * C * NVOX;   // tail: [B,3,N]

    mean_kernel    <<<dim3(3, B),                    256>>>(coords);
    scatter_kernel <<<dim3((NPTS + 255) / 256, B),   256>>>(feat, coords, norm_out);
    finalize_kernel<<<dim3(NVOX / 32, B),            256>>>(out);
}

// round 4
// speedup vs baseline: 1.3064x; 1.3064x over previous
#include <cuda_runtime.h>
#include <cstdint>

// Problem constants (fixed by setup_inputs)
#define B      8
#define C      64
#define NPTS   100000
#define RES    32
#define NVOX   (RES * RES * RES)   // 32768
#define NQ     (NPTS / 4)          // 25000 float4 quads per channel row
#define MEAN_SPLIT 32
#define MEAN_CHUNK 784             // ceil(25000/32) quads per block

// ---------------------------------------------------------------------------
// Scratch (__device__ globals: the sanctioned no-alloc scratch path).
// g_sums is channel-contiguous so one point's 64 adds are 16 aligned float4s.
// g_cnt / g_sums are zero at load and re-zeroed by finalize each replay.
// g_mean_part / g_mean are overwritten (plain stores) each replay.
// ---------------------------------------------------------------------------
__device__ float g_mean_part[B][3][MEAN_SPLIT];
__device__ float g_mean[B][3];
__device__ float g_cnt [B][NVOX];
__device__ float g_sums[B][NVOX][C];   // 64 MB

// ---------------------------------------------------------------------------
// Kernel 1a: partial sums for the coord mean.
// grid = (MEAN_SPLIT, 3, B), 256 threads, float4 loads. Deterministic
// (fixed shuffle tree per block, plain store of partial).
// ---------------------------------------------------------------------------
__global__ void __launch_bounds__(256) mean_part_kernel(const float* __restrict__ coords)
{
    const int z = blockIdx.x;
    const int d = blockIdx.y;
    const int b = blockIdx.z;
    const float4* p = (const float4*)(coords + (size_t)(b * 3 + d) * NPTS);

    const int start = z * MEAN_CHUNK;
    const int end   = min(NQ, start + MEAN_CHUNK);

    float s = 0.0f;
    for (int i = start + threadIdx.x; i < end; i += 256) {
        float4 v = p[i];
        s += (v.x + v.y) + (v.z + v.w);
    }

    __shared__ float sm[8];
    #pragma unroll
    for (int o = 16; o; o >>= 1)
        s += __shfl_down_sync(0xFFFFFFFFu, s, o);
    if ((threadIdx.x & 31) == 0) sm[threadIdx.x >> 5] = s;
    __syncthreads();
    if (threadIdx.x < 8) {
        s = sm[threadIdx.x];
        #pragma unroll
        for (int o = 4; o; o >>= 1)
            s += __shfl_down_sync(0xFFu, s, o);
        if (threadIdx.x == 0)
            g_mean_part[b][d][z] = s;
    }
}

// ---------------------------------------------------------------------------
// Kernel 1b: fold 32 partials per (b,d). One warp per (b,d), 24 warps.
// ---------------------------------------------------------------------------
__global__ void __launch_bounds__(768) mean_fold_kernel()
{
    const int w   = threadIdx.x >> 5;   // 0..23
    const int lid = threadIdx.x & 31;
    const int b = w / 3, d = w % 3;
    float s = g_mean_part[b][d][lid];
    #pragma unroll
    for (int o = 16; o; o >>= 1)
        s += __shfl_down_sync(0xFFFFFFFFu, s, o);
    if (lid == 0)
        g_mean[b][d] = s * (1.0f / (float)NPTS);
}

// ---------------------------------------------------------------------------
// Kernel 2: scatter, 4 points per thread.
//  - float4 coord loads / norm stores
//  - per channel-quad: one LDG.128 covers 4 points -> 16 LDG.128 per point-quad
//  - 16 red.global.add.v4.f32 per point into channel-contiguous scratch
// grid = (ceil(NQ/256), B), 256 threads.
// ---------------------------------------------------------------------------
__global__ void __launch_bounds__(256) scatter_kernel(const float* __restrict__ feat,
                                                      const float* __restrict__ coords,
                                                      float* __restrict__ norm_out)
{
    const int t  = blockIdx.x * blockDim.x + threadIdx.x;
    const int b  = blockIdx.y;
    const int n0 = t * 4;
    if (n0 >= NPTS) return;

    float w[3][4];
    #pragma unroll
    for (int d = 0; d < 3; d++) {
        const size_t off = (size_t)(b * 3 + d) * NPTS + n0;
        float4 v = *(const float4*)(coords + off);
        const float m = g_mean[b][d];
        float4 o;
        o.x = fminf(fmaxf((v.x - m + 1.0f) * 0.5f * (float)RES, 0.0f), (float)(RES - 1));
        o.y = fminf(fmaxf((v.y - m + 1.0f) * 0.5f * (float)RES, 0.0f), (float)(RES - 1));
        o.z = fminf(fmaxf((v.z - m + 1.0f) * 0.5f * (float)RES, 0.0f), (float)(RES - 1));
        o.w = fminf(fmaxf((v.w - m + 1.0f) * 0.5f * (float)RES, 0.0f), (float)(RES - 1));
        *(float4*)(norm_out + off) = o;
        w[d][0] = o.x; w[d][1] = o.y; w[d][2] = o.z; w[d][3] = o.w;
    }

    float* dst[4];
    #pragma unroll
    for (int j = 0; j < 4; j++) {
        // rintf = round-half-to-even = jnp.round
        const int idx = (int)rintf(w[0][j]) * (RES * RES)
                      + (int)rintf(w[1][j]) * RES
                      + (int)rintf(w[2][j]);
        dst[j] = &g_sums[b][idx][0];
        atomicAdd(&g_cnt[b][idx], 1.0f);
    }

    const float* f = feat + (size_t)b * C * NPTS + n0;

    #pragma unroll
    for (int c = 0; c < C; c += 4) {
        // 4 channels x 4 points
        float4 r0 = *(const float4*)(f + (size_t)(c + 0) * NPTS);
        float4 r1 = *(const float4*)(f + (size_t)(c + 1) * NPTS);
        float4 r2 = *(const float4*)(f + (size_t)(c + 2) * NPTS);
        float4 r3 = *(const float4*)(f + (size_t)(c + 3) * NPTS);
        asm volatile("red.global.add.v4.f32 [%0], {%1,%2,%3,%4};"
                     :: "l"(dst[0] + c), "f"(r0.x), "f"(r1.x), "f"(r2.x), "f"(r3.x) : "memory");
        asm volatile("red.global.add.v4.f32 [%0], {%1,%2,%3,%4};"
                     :: "l"(dst[1] + c), "f"(r0.y), "f"(r1.y), "f"(r2.y), "f"(r3.y) : "memory");
        asm volatile("red.global.add.v4.f32 [%0], {%1,%2,%3,%4};"
                     :: "l"(dst[2] + c), "f"(r0.z), "f"(r1.z), "f"(r2.z), "f"(r3.z) : "memory");
        asm volatile("red.global.add.v4.f32 [%0], {%1,%2,%3,%4};"
                     :: "l"(dst[3] + c), "f"(r0.w), "f"(r1.w), "f"(r2.w), "f"(r3.w) : "memory");
    }
}

// ---------------------------------------------------------------------------
// Kernel 3: finalize. Block = 32 voxels x 64 channels.
//  - float4 load of scratch + float4 zero-writeback (replay self-clean)
//  - scale by 1/max(cnt,1), transpose via padded (stride-65) smem
//  - float4 output stores in [chan][vox] layout
// grid = (NVOX/32, B), 256 threads.
// ---------------------------------------------------------------------------
__global__ void __launch_bounds__(256) finalize_kernel(float* __restrict__ vox_out)
{
    const int b   = blockIdx.y;
    const int v0  = blockIdx.x * 32;
    const int tid = threadIdx.x;

    __shared__ float sm[32 * 65];   // stride 65 -> conflict-free both phases
    __shared__ float inv[32];

    if (tid < 32) {
        float cnt = g_cnt[b][v0 + tid];
        g_cnt[b][v0 + tid] = 0.0f;
        inv[tid] = 1.0f / fmaxf(cnt, 1.0f);
    }
    __syncthreads();

    // 512 float4 quads in: quad q -> voxel v = q>>4, channel c4 = (q&15)*4
    #pragma unroll
    for (int k = 0; k < 2; k++) {
        const int q  = k * 256 + tid;
        const int v  = q >> 4;
        const int c  = (q & 15) * 4;
        float4* sp = (float4*)&g_sums[b][v0 + v][c];
        float4 val = *sp;
        *sp = make_float4(0.0f, 0.0f, 0.0f, 0.0f);
        const float s = inv[v];
        sm[v * 65 + c + 0] = val.x * s;
        sm[v * 65 + c + 1] = val.y * s;
        sm[v * 65 + c + 2] = val.z * s;
        sm[v * 65 + c + 3] = val.w * s;
    }
    __syncthreads();

    // 512 float4 quads out: quad q -> channel c = q>>3, voxel v4 = (q&7)*4
    #pragma unroll
    for (int k = 0; k < 2; k++) {
        const int q  = k * 256 + tid;
        const int c  = q >> 3;
        const int v4 = (q & 7) * 4;
        float4 o;
        o.x = sm[(v4 + 0) * 65 + c];
        o.y = sm[(v4 + 1) * 65 + c];
        o.z = sm[(v4 + 2) * 65 + c];
        o.w = sm[(v4 + 3) * 65 + c];
        *(float4*)(vox_out + ((size_t)(b * C + c)) * NVOX + v0 + v4) = o;
    }
}

// ---------------------------------------------------------------------------
// Launch. Inputs: [0]=features f32 [B,C,N], [1]=coords f32 [B,3,N].
// Output: vox [B,C,32,32,32] then norm_coords [B,3,N], both f32.
// ---------------------------------------------------------------------------
extern "C" void kernel_launch(void* const* d_in, const int* in_sizes, int n_in,
                              void* d_out, int out_size)
{
    const float* feat   = (const float*)d_in[0];
    const float* coords = (const float*)d_in[1];
    float* out      = (float*)d_out;
    float* norm_out = out + (size_t)B * C * NVOX;

    mean_part_kernel<<<dim3(MEAN_SPLIT, 3, B), 256>>>(coords);
    mean_fold_kernel<<<1, 768>>>();
    scatter_kernel  <<<dim3((NQ + 255) / 256, B), 256>>>(feat, coords, norm_out);
    finalize_kernel <<<dim3(NVOX / 32, B), 256>>>(out);
}